// round 8
// baseline (speedup 1.0000x reference)
#include <cuda_runtime.h>
#include <cuda_bf16.h>

#define N_NODES 100000
#define N_EDGES 1600000
#define D_IN    128
#define D_HID   64
#define NB      ((N_NODES + 255) / 256)   // 391 scan blocks

// Scratch (allocation-free rule: __device__ globals)
__device__ int   g_stride;                        // 1 = edge_index int32, 2 = int64
__device__ int   g_cnt [N_NODES];                 // incoming-edge count (no self-loop)
__device__ int   g_off [N_NODES];                 // CSR exclusive offsets
__device__ int   g_cur [N_NODES];                 // fill cursors
__device__ int   g_bsum[512];
__device__ int   g_boff[512];
__device__ int   g_csr [N_EDGES];                 // src ids bucketed by dst
__device__ float g_dis [N_NODES];                 // deg^{-1/2}
// h' rows stored channel-PAIRED: position p holds channels (p%32, p%32+32) as float2.
// Legal because aggregation is per-channel linear; epilogue indexes b1/W2 to match.
__device__ float2 g_h  [(size_t)N_NODES * 32];
__device__ float g_t   [N_NODES];                 // t' = (relu(out1)@W2)*dis

__device__ __forceinline__ int clampN(int v) {
    v = v < 0 ? 0 : v;
    return v >= N_NODES ? N_NODES - 1 : v;
}

// ---- packed f32x2 helpers (sm_100+; ptxas never auto-fuses FFMA2) ----
__device__ __forceinline__ void fma2(unsigned long long& a, unsigned long long b,
                                     unsigned long long c) {
    asm("fma.rn.f32x2 %0, %1, %2, %0;" : "+l"(a) : "l"(b), "l"(c));
}
__device__ __forceinline__ unsigned long long bcast2(float s) {
    unsigned long long r;
    asm("mov.b64 %0, {%1, %1};" : "=l"(r) : "f"(s));
    return r;
}
__device__ __forceinline__ float2 unpack2(unsigned long long a) {
    float2 r;
    asm("mov.b64 {%0, %1}, %2;" : "=f"(r.x), "=f"(r.y) : "l"(a));
    return r;
}

// ---------------------------------------------------------------- dtype detect
// int64 edge_index => odd 32-bit words are hi-words of ids < 100000 => all zero.
__global__ void k_detect(const int* __restrict__ ei) {
    __shared__ int nz;
    if (threadIdx.x == 0) nz = 0;
    __syncthreads();
    for (int i = threadIdx.x; i < 2048; i += 256) {
        size_t e = (size_t)i * (N_EDGES / 2048);
        if (ei[2 * e + 1] != 0) atomicAdd(&nz, 1);
    }
    __syncthreads();
    if (threadIdx.x == 0) g_stride = (nz == 0) ? 2 : 1;
}

__device__ __forceinline__ int edge_src(const int* ei, int e, int s) {
    return clampN(ei[(size_t)e * s]);
}
__device__ __forceinline__ int edge_dst(const int* ei, int e, int s) {
    return clampN(ei[(size_t)(N_EDGES + e) * s]);
}

// ---------------------------------------------------------------- degree / counts
__global__ void k_cnt_init() {
    int i = blockIdx.x * 256 + threadIdx.x;
    if (i < N_NODES) g_cnt[i] = 0;
}

__global__ void k_deg(const int* __restrict__ ei) {
    int e = blockIdx.x * 256 + threadIdx.x;
    if (e < N_EDGES) atomicAdd(&g_cnt[edge_dst(ei, e, g_stride)], 1);
}

__global__ void k_dis() {
    int i = blockIdx.x * 256 + threadIdx.x;
    if (i < N_NODES) g_dis[i] = rsqrtf((float)g_cnt[i] + 1.0f);
}

// ---------------------------------------------------------------- 3-phase exclusive scan
__global__ void k_scan1() {
    __shared__ int s[256];
    int t = threadIdx.x, i = blockIdx.x * 256 + t;
    int c = (i < N_NODES) ? g_cnt[i] : 0;
    s[t] = c; __syncthreads();
#pragma unroll
    for (int d = 1; d < 256; d <<= 1) {
        int v = (t >= d) ? s[t - d] : 0;
        __syncthreads();
        s[t] += v;
        __syncthreads();
    }
    if (i < N_NODES) g_off[i] = s[t] - c;
    if (t == 255) g_bsum[blockIdx.x] = s[255];
}

__global__ void k_scan2() {
    __shared__ int s[512];
    int t = threadIdx.x;
    int c = (t < NB) ? g_bsum[t] : 0;
    s[t] = c; __syncthreads();
#pragma unroll
    for (int d = 1; d < 512; d <<= 1) {
        int v = (t >= d) ? s[t - d] : 0;
        __syncthreads();
        s[t] += v;
        __syncthreads();
    }
    if (t < NB) g_boff[t] = s[t] - c;
}

__global__ void k_scan3() {
    int i = blockIdx.x * 256 + threadIdx.x;
    if (i < N_NODES) {
        int o = g_off[i] + g_boff[blockIdx.x];
        g_off[i] = o;
        g_cur[i] = o;
    }
}

// ---------------------------------------------------------------- CSR fill
__global__ void k_fill(const int* __restrict__ ei) {
    int e = blockIdx.x * 256 + threadIdx.x;
    if (e < N_EDGES) {
        int s = g_stride;
        int d = edge_dst(ei, e, s);
        int pos = atomicAdd(&g_cur[d], 1);
        g_csr[pos] = edge_src(ei, e, s);
    }
}

// ---------------------------------------------------------------- h' = (x@W1)*dis, channel-paired
// 8 warps, 4 rows/warp -> 32 rows/block. W1 packed as float2 pairs in smem.
__global__ void k_gemm(const float* __restrict__ x, const float* __restrict__ W1) {
    __shared__ float2 sW[D_IN * 32];   // sW[k*32 + c] = {W1[k][c], W1[k][c+32]}  (32 KB)
    __shared__ float  sx[32 * D_IN];   // 16 KB
    int tid = threadIdx.x;
    for (int idx = tid; idx < D_IN * 32; idx += 256) {
        int k = idx >> 5, c = idx & 31;
        sW[idx] = make_float2(W1[k * D_HID + c], W1[k * D_HID + c + 32]);
    }
    int base = blockIdx.x * 32;
    for (int idx = tid; idx < 32 * D_IN; idx += 256) {
        int r = base + (idx >> 7);
        sx[idx] = (r < N_NODES) ? x[(size_t)r * D_IN + (idx & 127)] : 0.f;
    }
    __syncthreads();

    int warp = tid >> 5, lane = tid & 31;
    const float* xs = &sx[warp * 4 * D_IN];
    unsigned long long a0 = 0ull, a1 = 0ull, a2 = 0ull, a3 = 0ull;  // {0.f,0.f} packed

    for (int k = 0; k < D_IN; k += 4) {
        float4 v0 = *reinterpret_cast<const float4*>(&xs[k]);
        float4 v1 = *reinterpret_cast<const float4*>(&xs[D_IN + k]);
        float4 v2 = *reinterpret_cast<const float4*>(&xs[2 * D_IN + k]);
        float4 v3 = *reinterpret_cast<const float4*>(&xs[3 * D_IN + k]);
#pragma unroll
        for (int kk = 0; kk < 4; kk++) {
            unsigned long long w =
                *reinterpret_cast<const unsigned long long*>(&sW[(k + kk) * 32 + lane]);
            float s0 = (&v0.x)[kk], s1 = (&v1.x)[kk], s2 = (&v2.x)[kk], s3 = (&v3.x)[kk];
            fma2(a0, w, bcast2(s0));
            fma2(a1, w, bcast2(s1));
            fma2(a2, w, bcast2(s2));
            fma2(a3, w, bcast2(s3));
        }
    }

    int row = base + warp * 4;
#define GNN_EPI(R, A)                                            \
    {                                                            \
        int rr = row + (R);                                      \
        if (rr < N_NODES) {                                      \
            float dd = g_dis[rr];                                \
            float2 u = unpack2(A);                               \
            u.x *= dd; u.y *= dd;                                \
            g_h[(size_t)rr * 32 + lane] = u;                     \
        }                                                        \
    }
    GNN_EPI(0, a0)
    GNN_EPI(1, a1)
    GNN_EPI(2, a2)
    GNN_EPI(3, a3)
#undef GNN_EPI
}

// ---------------------------------------------------------------- layer-1 gather + node op (fused)
// One warp per dst node, one LDG.64 per lane per neighbor row, 8-deep unroll for MLP.
__global__ void k_gather1(const float* __restrict__ b1, const float* __restrict__ W2) {
    int n = (blockIdx.x * 256 + threadIdx.x) >> 5;
    int lane = threadIdx.x & 31;
    if (n >= N_NODES) return;

    float2 a = g_h[(size_t)n * 32 + lane];          // self-loop init
    float ax = a.x, ay = a.y;

    int beg = g_off[n];
    int end = beg + g_cnt[n];
    int j = beg;
    for (; j + 7 < end; j += 8) {
        int s0 = g_csr[j],     s1 = g_csr[j + 1], s2 = g_csr[j + 2], s3 = g_csr[j + 3];
        int s4 = g_csr[j + 4], s5 = g_csr[j + 5], s6 = g_csr[j + 6], s7 = g_csr[j + 7];
        float2 p0 = g_h[(size_t)s0 * 32 + lane], p1 = g_h[(size_t)s1 * 32 + lane];
        float2 p2 = g_h[(size_t)s2 * 32 + lane], p3 = g_h[(size_t)s3 * 32 + lane];
        float2 p4 = g_h[(size_t)s4 * 32 + lane], p5 = g_h[(size_t)s5 * 32 + lane];
        float2 p6 = g_h[(size_t)s6 * 32 + lane], p7 = g_h[(size_t)s7 * 32 + lane];
        ax += ((p0.x + p1.x) + (p2.x + p3.x)) + ((p4.x + p5.x) + (p6.x + p7.x));
        ay += ((p0.y + p1.y) + (p2.y + p3.y)) + ((p4.y + p5.y) + (p6.y + p7.y));
    }
    for (; j < end; j++) {
        float2 p = g_h[(size_t)g_csr[j] * 32 + lane];
        ax += p.x; ay += p.y;
    }

    float d = g_dis[n];
    float z0 = fmaxf(fmaf(d, ax, b1[lane]),      0.f);   // channel lane
    float z1 = fmaxf(fmaf(d, ay, b1[lane + 32]), 0.f);   // channel lane+32
    float t = z0 * W2[lane] + z1 * W2[lane + 32];
#pragma unroll
    for (int off = 16; off; off >>= 1)
        t += __shfl_xor_sync(0xffffffffu, t, off);
    if (lane == 0) g_t[n] = t * d;
}

// ---------------------------------------------------------------- layer-2 gather + padded output
__global__ void k_l2(float* __restrict__ out, const float* __restrict__ b2) {
    int n = (blockIdx.x * 256 + threadIdx.x) >> 5;
    int lane = threadIdx.x & 31;
    if (n >= N_NODES) return;

    int beg = g_off[n];
    int end = beg + g_cnt[n];
    float sum = lane ? 0.f : g_t[n];                    // self-loop on lane 0
    for (int j = beg + lane; j < end; j += 32)
        sum += g_t[g_csr[j]];
#pragma unroll
    for (int off = 16; off; off >>= 1)
        sum += __shfl_xor_sync(0xffffffffu, sum, off);

    float y = g_dis[n] * sum + b2[0];
    float4 v = make_float4(0.f, 0.f, 0.f, 0.f);
    if (lane == 0) v.x = y;
    reinterpret_cast<float4*>(out)[(size_t)n * 32 + lane] = v;   // 128 floats/row
}

// ----------------------------------------------------------------
extern "C" void kernel_launch(void* const* d_in, const int* in_sizes, int n_in,
                              void* d_out, int out_size) {
    const float* x   = (const float*)d_in[0];
    const int*   ei  = (const int*)d_in[1];    // int32 OR int64 (detected on device)
    const float* W1  = (const float*)d_in[2];
    const float* b1  = (const float*)d_in[3];
    const float* W2  = (const float*)d_in[4];
    const float* b2  = (const float*)d_in[5];
    float*       out = (float*)d_out;

    k_detect  <<<1, 256>>>(ei);
    k_cnt_init<<<NB, 256>>>();
    k_deg     <<<(N_EDGES + 255) / 256, 256>>>(ei);
    k_dis     <<<NB, 256>>>();
    k_scan1   <<<NB, 256>>>();
    k_scan2   <<<1, 512>>>();
    k_scan3   <<<NB, 256>>>();
    k_fill    <<<(N_EDGES + 255) / 256, 256>>>(ei);
    k_gemm    <<<(N_NODES + 31) / 32, 256>>>(x, W1);
    k_gather1 <<<(N_NODES * 32 + 255) / 256, 256>>>(b1, W2);
    k_l2      <<<(N_NODES * 32 + 255) / 256, 256>>>(out, b2);
}

// round 10
// speedup vs baseline: 1.0436x; 1.0436x over previous
#include <cuda_runtime.h>
#include <cuda_bf16.h>

#define N_NODES 100000
#define N_EDGES 1600000
#define D_IN    128
#define D_HID   64
#define NB      ((N_NODES + 255) / 256)   // 391 scan blocks

// Scratch (allocation-free rule: __device__ globals)
__device__ int   g_cnt [N_NODES];                 // incoming-edge count (no self-loop)
__device__ int   g_off [N_NODES];                 // CSR exclusive offsets
__device__ int   g_cur [N_NODES];                 // fill cursors
__device__ int   g_bsum[512];
__device__ int   g_boff[512];
__device__ int   g_csr [N_EDGES];                 // src ids bucketed by dst
__device__ float g_dis [N_NODES];                 // deg^{-1/2}
// h' rows channel-paired: slot p = channels (p, p+32) as float2 (256 B/row).
__device__ float2 g_h  [(size_t)N_NODES * 32];
__device__ float g_t   [N_NODES];                 // t' = (relu(out1)@W2)*dis

__device__ __forceinline__ int clampN(int v) {
    v = v < 0 ? 0 : v;
    return v >= N_NODES ? N_NODES - 1 : v;
}

// edge_index is int32 (confirmed: R7 passed via the int32 path on this dataset)
__device__ __forceinline__ int edge_src(const int* ei, int e) { return clampN(ei[e]); }
__device__ __forceinline__ int edge_dst(const int* ei, int e) { return clampN(ei[N_EDGES + e]); }

// ---------------------------------------------------------------- counts
__global__ void k_cnt_init() {
    int i = blockIdx.x * 256 + threadIdx.x;
    if (i < N_NODES) g_cnt[i] = 0;
}

__global__ void k_deg(const int* __restrict__ ei) {
    int e = blockIdx.x * 256 + threadIdx.x;
    if (e < N_EDGES) atomicAdd(&g_cnt[edge_dst(ei, e)], 1);
}

__global__ void k_dis() {
    int i = blockIdx.x * 256 + threadIdx.x;
    if (i < N_NODES) g_dis[i] = rsqrtf((float)g_cnt[i] + 1.0f);   // +1 self-loop
}

// ---------------------------------------------------------------- h' = (x@W1)*dis  [PROFILED SLOT #4]
// 8 warps, 4 rows/warp -> 32 rows/block. Scalar FFMA inner loop (FFMA2 was mov-bound, R8).
__global__ void k_gemm(const float* __restrict__ x, const float* __restrict__ W1) {
    __shared__ float sW[D_IN * D_HID];   // 32 KB
    __shared__ float sx[32 * D_IN];      // 16 KB
    int tid = threadIdx.x;
    for (int idx = tid; idx < D_IN * D_HID; idx += 256) sW[idx] = W1[idx];
    int base = blockIdx.x * 32;
    for (int idx = tid; idx < 32 * D_IN; idx += 256) {
        int r = base + (idx >> 7);
        sx[idx] = (r < N_NODES) ? x[(size_t)r * D_IN + (idx & 127)] : 0.f;
    }
    __syncthreads();

    int warp = tid >> 5, lane = tid & 31;
    const float* xs = &sx[warp * 4 * D_IN];
    float a00 = 0.f, a01 = 0.f, a10 = 0.f, a11 = 0.f;
    float a20 = 0.f, a21 = 0.f, a30 = 0.f, a31 = 0.f;

#pragma unroll 8
    for (int k = 0; k < D_IN; k++) {
        float w0 = sW[k * D_HID + lane];
        float w1 = sW[k * D_HID + lane + 32];
        float v0 = xs[k];
        float v1 = xs[D_IN + k];
        float v2 = xs[2 * D_IN + k];
        float v3 = xs[3 * D_IN + k];
        a00 += v0 * w0; a01 += v0 * w1;
        a10 += v1 * w0; a11 += v1 * w1;
        a20 += v2 * w0; a21 += v2 * w1;
        a30 += v3 * w0; a31 += v3 * w1;
    }

    int row = base + warp * 4;
#define GNN_EPI(R, A0, A1)                                       \
    {                                                            \
        int rr = row + (R);                                      \
        if (rr < N_NODES) {                                      \
            float dd = g_dis[rr];                                \
            g_h[(size_t)rr * 32 + lane] =                        \
                make_float2((A0) * dd, (A1) * dd);               \
        }                                                        \
    }
    GNN_EPI(0, a00, a01)
    GNN_EPI(1, a10, a11)
    GNN_EPI(2, a20, a21)
    GNN_EPI(3, a30, a31)
#undef GNN_EPI
}

// ---------------------------------------------------------------- 3-phase exclusive scan
__global__ void k_scan1() {
    __shared__ int s[256];
    int t = threadIdx.x, i = blockIdx.x * 256 + t;
    int c = (i < N_NODES) ? g_cnt[i] : 0;
    s[t] = c; __syncthreads();
#pragma unroll
    for (int d = 1; d < 256; d <<= 1) {
        int v = (t >= d) ? s[t - d] : 0;
        __syncthreads();
        s[t] += v;
        __syncthreads();
    }
    if (i < N_NODES) g_off[i] = s[t] - c;
    if (t == 255) g_bsum[blockIdx.x] = s[255];
}

__global__ void k_scan2() {
    __shared__ int s[512];
    int t = threadIdx.x;
    int c = (t < NB) ? g_bsum[t] : 0;
    s[t] = c; __syncthreads();
#pragma unroll
    for (int d = 1; d < 512; d <<= 1) {
        int v = (t >= d) ? s[t - d] : 0;
        __syncthreads();
        s[t] += v;
        __syncthreads();
    }
    if (t < NB) g_boff[t] = s[t] - c;
}

__global__ void k_scan3() {
    int i = blockIdx.x * 256 + threadIdx.x;
    if (i < N_NODES) {
        int o = g_off[i] + g_boff[blockIdx.x];
        g_off[i] = o;
        g_cur[i] = o;
    }
}

// ---------------------------------------------------------------- CSR fill (int atomics only)
__global__ void k_fill(const int* __restrict__ ei) {
    int e = blockIdx.x * 256 + threadIdx.x;
    if (e < N_EDGES) {
        int d = edge_dst(ei, e);
        int pos = atomicAdd(&g_cur[d], 1);
        g_csr[pos] = edge_src(ei, e);
    }
}

// ---------------------------------------------------------------- layer-1 gather + node op (fused)
// One warp per dst node; neighbor rows as one LDG.64/lane; csr indices via int4.
__global__ void k_gather1(const float* __restrict__ b1, const float* __restrict__ W2) {
    int n = (blockIdx.x * 256 + threadIdx.x) >> 5;
    int lane = threadIdx.x & 31;
    if (n >= N_NODES) return;

    float2 a = g_h[(size_t)n * 32 + lane];          // self-loop init
    float ax = a.x, ay = a.y;

    int j   = g_off[n];
    int end = j + g_cnt[n];

    // scalar head to 16B alignment
    while (j < end && (j & 3)) {
        float2 p = g_h[(size_t)g_csr[j] * 32 + lane];
        ax += p.x; ay += p.y;
        j++;
    }
    // 8 edges per iter: 2 LDG.128 index loads + 8 LDG.64 row loads
    for (; j + 7 < end; j += 8) {
        int4 c0 = *reinterpret_cast<const int4*>(&g_csr[j]);
        int4 c1 = *reinterpret_cast<const int4*>(&g_csr[j + 4]);
        float2 p0 = g_h[(size_t)c0.x * 32 + lane], p1 = g_h[(size_t)c0.y * 32 + lane];
        float2 p2 = g_h[(size_t)c0.z * 32 + lane], p3 = g_h[(size_t)c0.w * 32 + lane];
        float2 p4 = g_h[(size_t)c1.x * 32 + lane], p5 = g_h[(size_t)c1.y * 32 + lane];
        float2 p6 = g_h[(size_t)c1.z * 32 + lane], p7 = g_h[(size_t)c1.w * 32 + lane];
        ax += ((p0.x + p1.x) + (p2.x + p3.x)) + ((p4.x + p5.x) + (p6.x + p7.x));
        ay += ((p0.y + p1.y) + (p2.y + p3.y)) + ((p4.y + p5.y) + (p6.y + p7.y));
    }
    for (; j + 3 < end; j += 4) {
        int4 c0 = *reinterpret_cast<const int4*>(&g_csr[j]);
        float2 p0 = g_h[(size_t)c0.x * 32 + lane], p1 = g_h[(size_t)c0.y * 32 + lane];
        float2 p2 = g_h[(size_t)c0.z * 32 + lane], p3 = g_h[(size_t)c0.w * 32 + lane];
        ax += (p0.x + p1.x) + (p2.x + p3.x);
        ay += (p0.y + p1.y) + (p2.y + p3.y);
    }
    for (; j < end; j++) {
        float2 p = g_h[(size_t)g_csr[j] * 32 + lane];
        ax += p.x; ay += p.y;
    }

    float d = g_dis[n];
    float z0 = fmaxf(fmaf(d, ax, b1[lane]),      0.f);
    float z1 = fmaxf(fmaf(d, ay, b1[lane + 32]), 0.f);
    float t = z0 * W2[lane] + z1 * W2[lane + 32];
#pragma unroll
    for (int off = 16; off; off >>= 1)
        t += __shfl_xor_sync(0xffffffffu, t, off);
    if (lane == 0) g_t[n] = t * d;
}

// ---------------------------------------------------------------- layer-2 gather + padded output
__global__ void k_l2(float* __restrict__ out, const float* __restrict__ b2) {
    int n = (blockIdx.x * 256 + threadIdx.x) >> 5;
    int lane = threadIdx.x & 31;
    if (n >= N_NODES) return;

    int beg = g_off[n];
    int end = beg + g_cnt[n];
    float sum = lane ? 0.f : g_t[n];                    // self-loop on lane 0
    for (int j = beg + lane; j < end; j += 32)
        sum += g_t[g_csr[j]];
#pragma unroll
    for (int off = 16; off; off >>= 1)
        sum += __shfl_xor_sync(0xffffffffu, sum, off);

    float y = g_dis[n] * sum + b2[0];
    float4 v = make_float4(0.f, 0.f, 0.f, 0.f);
    if (lane == 0) v.x = y;
    reinterpret_cast<float4*>(out)[(size_t)n * 32 + lane] = v;   // 128 floats/row
}

// ----------------------------------------------------------------
extern "C" void kernel_launch(void* const* d_in, const int* in_sizes, int n_in,
                              void* d_out, int out_size) {
    const float* x   = (const float*)d_in[0];
    const int*   ei  = (const int*)d_in[1];    // int32 [2, E]
    const float* W1  = (const float*)d_in[2];
    const float* b1  = (const float*)d_in[3];
    const float* W2  = (const float*)d_in[4];
    const float* b2  = (const float*)d_in[5];
    float*       out = (float*)d_out;

    k_cnt_init<<<NB, 256>>>();                              // 1
    k_deg     <<<(N_EDGES + 255) / 256, 256>>>(ei);         // 2
    k_dis     <<<NB, 256>>>();                              // 3
    k_gemm    <<<(N_NODES + 31) / 32, 256>>>(x, W1);        // 4  <- profiled slot
    k_scan1   <<<NB, 256>>>();                              // 5
    k_scan2   <<<1, 512>>>();                               // 6
    k_scan3   <<<NB, 256>>>();                              // 7
    k_fill    <<<(N_EDGES + 255) / 256, 256>>>(ei);         // 8
    k_gather1 <<<(N_NODES * 32 + 255) / 256, 256>>>(b1, W2);// 9
    k_l2      <<<(N_NODES * 32 + 255) / 256, 256>>>(out, b2);// 10
}

// round 12
// speedup vs baseline: 1.0736x; 1.0288x over previous
#include <cuda_runtime.h>
#include <cuda_bf16.h>

#define N_NODES 100000
#define N_EDGES 1600000
#define D_IN    128
#define D_HID   64
#define NB      ((N_NODES + 255) / 256)   // 391 scan blocks

// Scratch (allocation-free rule: __device__ globals)
__device__ int   g_cnt [N_NODES];                 // incoming-edge count (no self-loop)
__device__ int   g_off [N_NODES];                 // CSR exclusive offsets
__device__ int   g_cur [N_NODES];                 // fill cursors
__device__ int   g_bsum[512];
__device__ int   g_boff[512];
__device__ int   g_csr [N_EDGES];                 // src ids bucketed by dst
__device__ float g_dis [N_NODES];                 // deg^{-1/2}
// h' rows channel-paired: slot p = channels (p, p+32) as float2 (256 B/row).
__device__ float2 g_h  [(size_t)N_NODES * 32];
__device__ float g_t   [N_NODES];                 // t' = (relu(out1)@W2)*dis

__device__ __forceinline__ int clampN(int v) {
    v = v < 0 ? 0 : v;
    return v >= N_NODES ? N_NODES - 1 : v;
}

// edge_index is int32 (confirmed: R7 passed via the int32 path on this dataset)
__device__ __forceinline__ int edge_src(const int* ei, int e) { return clampN(ei[e]); }
__device__ __forceinline__ int edge_dst(const int* ei, int e) { return clampN(ei[N_EDGES + e]); }

// ---------------------------------------------------------------- counts
__global__ void k_cnt_init() {
    int i = blockIdx.x * 256 + threadIdx.x;
    if (i < N_NODES) g_cnt[i] = 0;
}

__global__ void k_deg(const int* __restrict__ ei) {
    int e = blockIdx.x * 256 + threadIdx.x;
    if (e < N_EDGES) atomicAdd(&g_cnt[edge_dst(ei, e)], 1);
}

__global__ void k_dis() {
    int i = blockIdx.x * 256 + threadIdx.x;
    if (i < N_NODES) g_dis[i] = rsqrtf((float)g_cnt[i] + 1.0f);   // +1 self-loop
}

// ---------------------------------------------------------------- h' = (x@W1)*dis  [PROFILED SLOT #4]
// 8 warps, 4 rows/warp, 32 rows/block (3125*32 == 100000 exactly, no row guards).
// W1 in smem as channel-paired float2 (1 LDS.64/k serves both output channels).
// x read DIRECTLY from gmem as broadcast LDG.128 (no cross-warp reuse -> smem
// staging was pure crossbar waste; this was the R10 L1=52% bottleneck).
__global__ void __launch_bounds__(256) k_gemm(const float* __restrict__ x,
                                              const float* __restrict__ W1) {
    __shared__ float2 sW[D_IN * 32];   // sW[k*32+c] = {W1[k][c], W1[k][c+32]}  (32 KB)
    int tid = threadIdx.x;
    for (int idx = tid; idx < D_IN * 32; idx += 256) {
        int k = idx >> 5, c = idx & 31;
        sW[idx] = make_float2(W1[k * D_HID + c], W1[k * D_HID + c + 32]);
    }
    __syncthreads();

    int warp = tid >> 5, lane = tid & 31;
    int row = blockIdx.x * 32 + warp * 4;

    const float4* x0 = reinterpret_cast<const float4*>(x + (size_t)(row + 0) * D_IN);
    const float4* x1 = reinterpret_cast<const float4*>(x + (size_t)(row + 1) * D_IN);
    const float4* x2 = reinterpret_cast<const float4*>(x + (size_t)(row + 2) * D_IN);
    const float4* x3 = reinterpret_cast<const float4*>(x + (size_t)(row + 3) * D_IN);

    float2 a0 = make_float2(0.f, 0.f), a1 = a0, a2 = a0, a3 = a0;

#pragma unroll 4
    for (int kb = 0; kb < D_IN / 4; kb++) {        // 4 k per iter
        float4 v0 = __ldg(&x0[kb]);                // broadcast loads: 1 sector each
        float4 v1 = __ldg(&x1[kb]);
        float4 v2 = __ldg(&x2[kb]);
        float4 v3 = __ldg(&x3[kb]);
#pragma unroll
        for (int kk = 0; kk < 4; kk++) {
            float2 w = sW[(kb * 4 + kk) * 32 + lane];   // LDS.64, conflict-free
            float s0 = (&v0.x)[kk], s1 = (&v1.x)[kk];
            float s2 = (&v2.x)[kk], s3 = (&v3.x)[kk];
            a0.x = fmaf(s0, w.x, a0.x); a0.y = fmaf(s0, w.y, a0.y);
            a1.x = fmaf(s1, w.x, a1.x); a1.y = fmaf(s1, w.y, a1.y);
            a2.x = fmaf(s2, w.x, a2.x); a2.y = fmaf(s2, w.y, a2.y);
            a3.x = fmaf(s3, w.x, a3.x); a3.y = fmaf(s3, w.y, a3.y);
        }
    }

#define GNN_EPI(R, A)                                            \
    {                                                            \
        int rr = row + (R);                                      \
        float dd = g_dis[rr];                                    \
        g_h[(size_t)rr * 32 + lane] =                            \
            make_float2((A).x * dd, (A).y * dd);                 \
    }
    GNN_EPI(0, a0)
    GNN_EPI(1, a1)
    GNN_EPI(2, a2)
    GNN_EPI(3, a3)
#undef GNN_EPI
}

// ---------------------------------------------------------------- 3-phase exclusive scan
__global__ void k_scan1() {
    __shared__ int s[256];
    int t = threadIdx.x, i = blockIdx.x * 256 + t;
    int c = (i < N_NODES) ? g_cnt[i] : 0;
    s[t] = c; __syncthreads();
#pragma unroll
    for (int d = 1; d < 256; d <<= 1) {
        int v = (t >= d) ? s[t - d] : 0;
        __syncthreads();
        s[t] += v;
        __syncthreads();
    }
    if (i < N_NODES) g_off[i] = s[t] - c;
    if (t == 255) g_bsum[blockIdx.x] = s[255];
}

__global__ void k_scan2() {
    __shared__ int s[512];
    int t = threadIdx.x;
    int c = (t < NB) ? g_bsum[t] : 0;
    s[t] = c; __syncthreads();
#pragma unroll
    for (int d = 1; d < 512; d <<= 1) {
        int v = (t >= d) ? s[t - d] : 0;
        __syncthreads();
        s[t] += v;
        __syncthreads();
    }
    if (t < NB) g_boff[t] = s[t] - c;
}

__global__ void k_scan3() {
    int i = blockIdx.x * 256 + threadIdx.x;
    if (i < N_NODES) {
        int o = g_off[i] + g_boff[blockIdx.x];
        g_off[i] = o;
        g_cur[i] = o;
    }
}

// ---------------------------------------------------------------- CSR fill (int atomics only)
__global__ void k_fill(const int* __restrict__ ei) {
    int e = blockIdx.x * 256 + threadIdx.x;
    if (e < N_EDGES) {
        int d = edge_dst(ei, e);
        int pos = atomicAdd(&g_cur[d], 1);
        g_csr[pos] = edge_src(ei, e);
    }
}

// ---------------------------------------------------------------- layer-1 gather + node op (fused)
// One warp per dst node; neighbor rows as one LDG.64/lane; csr indices via int4.
__global__ void k_gather1(const float* __restrict__ b1, const float* __restrict__ W2) {
    int n = (blockIdx.x * 256 + threadIdx.x) >> 5;
    int lane = threadIdx.x & 31;
    if (n >= N_NODES) return;

    float2 a = g_h[(size_t)n * 32 + lane];          // self-loop init
    float ax = a.x, ay = a.y;

    int j   = g_off[n];
    int end = j + g_cnt[n];

    // scalar head to 16B alignment
    while (j < end && (j & 3)) {
        float2 p = g_h[(size_t)g_csr[j] * 32 + lane];
        ax += p.x; ay += p.y;
        j++;
    }
    // 8 edges per iter: 2 LDG.128 index loads + 8 LDG.64 row loads
    for (; j + 7 < end; j += 8) {
        int4 c0 = *reinterpret_cast<const int4*>(&g_csr[j]);
        int4 c1 = *reinterpret_cast<const int4*>(&g_csr[j + 4]);
        float2 p0 = g_h[(size_t)c0.x * 32 + lane], p1 = g_h[(size_t)c0.y * 32 + lane];
        float2 p2 = g_h[(size_t)c0.z * 32 + lane], p3 = g_h[(size_t)c0.w * 32 + lane];
        float2 p4 = g_h[(size_t)c1.x * 32 + lane], p5 = g_h[(size_t)c1.y * 32 + lane];
        float2 p6 = g_h[(size_t)c1.z * 32 + lane], p7 = g_h[(size_t)c1.w * 32 + lane];
        ax += ((p0.x + p1.x) + (p2.x + p3.x)) + ((p4.x + p5.x) + (p6.x + p7.x));
        ay += ((p0.y + p1.y) + (p2.y + p3.y)) + ((p4.y + p5.y) + (p6.y + p7.y));
    }
    for (; j + 3 < end; j += 4) {
        int4 c0 = *reinterpret_cast<const int4*>(&g_csr[j]);
        float2 p0 = g_h[(size_t)c0.x * 32 + lane], p1 = g_h[(size_t)c0.y * 32 + lane];
        float2 p2 = g_h[(size_t)c0.z * 32 + lane], p3 = g_h[(size_t)c0.w * 32 + lane];
        ax += (p0.x + p1.x) + (p2.x + p3.x);
        ay += (p0.y + p1.y) + (p2.y + p3.y);
    }
    for (; j < end; j++) {
        float2 p = g_h[(size_t)g_csr[j] * 32 + lane];
        ax += p.x; ay += p.y;
    }

    float d = g_dis[n];
    float z0 = fmaxf(fmaf(d, ax, b1[lane]),      0.f);
    float z1 = fmaxf(fmaf(d, ay, b1[lane + 32]), 0.f);
    float t = z0 * W2[lane] + z1 * W2[lane + 32];
#pragma unroll
    for (int off = 16; off; off >>= 1)
        t += __shfl_xor_sync(0xffffffffu, t, off);
    if (lane == 0) g_t[n] = t * d;
}

// ---------------------------------------------------------------- layer-2 gather + padded output
__global__ void k_l2(float* __restrict__ out, const float* __restrict__ b2) {
    int n = (blockIdx.x * 256 + threadIdx.x) >> 5;
    int lane = threadIdx.x & 31;
    if (n >= N_NODES) return;

    int beg = g_off[n];
    int end = beg + g_cnt[n];
    float sum = lane ? 0.f : g_t[n];                    // self-loop on lane 0
    for (int j = beg + lane; j < end; j += 32)
        sum += g_t[g_csr[j]];
#pragma unroll
    for (int off = 16; off; off >>= 1)
        sum += __shfl_xor_sync(0xffffffffu, sum, off);

    float y = g_dis[n] * sum + b2[0];
    float4 v = make_float4(0.f, 0.f, 0.f, 0.f);
    if (lane == 0) v.x = y;
    reinterpret_cast<float4*>(out)[(size_t)n * 32 + lane] = v;   // 128 floats/row
}

// ----------------------------------------------------------------
extern "C" void kernel_launch(void* const* d_in, const int* in_sizes, int n_in,
                              void* d_out, int out_size) {
    const float* x   = (const float*)d_in[0];
    const int*   ei  = (const int*)d_in[1];    // int32 [2, E]
    const float* W1  = (const float*)d_in[2];
    const float* b1  = (const float*)d_in[3];
    const float* W2  = (const float*)d_in[4];
    const float* b2  = (const float*)d_in[5];
    float*       out = (float*)d_out;

    k_cnt_init<<<NB, 256>>>();                              // 1
    k_deg     <<<(N_EDGES + 255) / 256, 256>>>(ei);         // 2
    k_dis     <<<NB, 256>>>();                              // 3
    k_gemm    <<<N_NODES / 32, 256>>>(x, W1);               // 4  <- profiled slot
    k_scan1   <<<NB, 256>>>();                              // 5
    k_scan2   <<<1, 512>>>();                               // 6
    k_scan3   <<<NB, 256>>>();                              // 7
    k_fill    <<<(N_EDGES + 255) / 256, 256>>>(ei);         // 8
    k_gather1 <<<(N_NODES * 32 + 255) / 256, 256>>>(b1, W2);// 9
    k_l2      <<<(N_NODES * 32 + 255) / 256, 256>>>(out, b2);// 10
}